// round 8
// baseline (speedup 1.0000x reference)
#include <cuda_runtime.h>
#include <cstdint>
#include <math.h>

typedef unsigned long long ull;

// Problem constants
#define B_    32
#define L_    2048
#define I_    256
#define H_    512
#define HX    768      // H + I
#define N3    1536     // 3*H (z | r | w)
#define NCG   16       // column groups (CTAs per batch group)
#define NBG   8        // batch groups
#define BPG   4        // batches per group
#define CPG   32       // gate columns per CTA per gate
#define NTHR  512

// ---------------- device scratch ----------------
__device__ float g_X[(size_t)L_ * B_ * N3];   // precomputed x-contributions
__device__ float g_rh[2][B_ * H_];            // r*h exchange (parity buffers)
__device__ unsigned g_hflag[NBG * 32];        // h-step flags (16 used per group, 128B line)
__device__ unsigned g_rhflag[NBG * 32];       // rh-step flags

// ---------------- smem layout (float offsets): weights only ----------------
#define WR_F 0                   // 32 x 512
#define WZ_F (32 * 512)
#define WW_F (64 * 512)
#define SM_FLOATS (96 * 512)
#define SMEM_BYTES (SM_FLOATS * 4)   // 196,608 B

// ---------------- asm helpers ----------------
__device__ __forceinline__ uint32_t smem_u32(const void* p) {
    uint32_t a;
    asm("{ .reg .u64 t; cvta.to.shared.u64 t, %1; cvt.u32.u64 %0, t; }" : "=r"(a) : "l"(p));
    return a;
}
__device__ __forceinline__ ull lds64(uint32_t a) {
    ull v;
    asm volatile("ld.shared.b64 %0, [%1];" : "=l"(v) : "r"(a));
    return v;
}
__device__ __forceinline__ ull ldg64cg(const void* p) {
    ull v;
    asm volatile("ld.global.cg.b64 %0, [%1];" : "=l"(v) : "l"(p));
    return v;
}
__device__ __forceinline__ float ldg32cg(const void* p) {
    float v;
    asm volatile("ld.global.cg.f32 %0, [%1];" : "=f"(v) : "l"(p));
    return v;
}
__device__ __forceinline__ void fma2(ull& acc, ull a, ull b) {
    asm volatile("fma.rn.f32x2 %0, %1, %2, %0;" : "+l"(acc) : "l"(a), "l"(b));
}
__device__ __forceinline__ float sum2(ull v) {
    float lo, hi;
    asm("mov.b64 {%0, %1}, %2;" : "=f"(lo), "=f"(hi) : "l"(v));
    return lo + hi;
}
__device__ __forceinline__ void st_release(unsigned* p, unsigned v) {
    asm volatile("st.release.gpu.u32 [%0], %1;" :: "l"(p), "r"(v) : "memory");
}
__device__ __forceinline__ unsigned ld_acquire(const unsigned* p) {
    unsigned v;
    asm volatile("ld.acquire.gpu.u32 %0, [%1];" : "=r"(v) : "l"(p) : "memory");
    return v;
}

// warp 0 polls 16 flags (one 128B line); call __syncthreads() after.
__device__ __forceinline__ void wait_flags(const unsigned* flags, unsigned target, int lane) {
    const unsigned* p = flags + (lane & 15);
    unsigned v;
    do {
        v = ld_acquire(p);
    } while (!__all_sync(0xffffffffu, (int)(v - target) >= 0));
}

// ---------------- warp reduction: 8 chains (2 cols x 4 batches) over 32 lanes -----
// After return: each 4-lane group (lane>>2 fixed) holds output o=(lane>>2)&7 in a[0];
// o = c*4 + b with c=(lane>>4)&1, b=(lane>>2)&3.
__device__ __forceinline__ void reduce8(float a[8], int lane) {
#pragma unroll
    for (int o = 0; o < 4; o++) {
        bool hi = (lane & 16);
        float send = hi ? a[o] : a[o + 4];
        float keep = hi ? a[o + 4] : a[o];
        a[o] = keep + __shfl_xor_sync(0xffffffffu, send, 16);
    }
#pragma unroll
    for (int o = 0; o < 2; o++) {
        bool hi = (lane & 8);
        float send = hi ? a[o] : a[o + 2];
        float keep = hi ? a[o + 2] : a[o];
        a[o] = keep + __shfl_xor_sync(0xffffffffu, send, 8);
    }
    {
        bool hi = (lane & 4);
        float send = hi ? a[0] : a[1];
        float keep = hi ? a[1] : a[0];
        a[0] = keep + __shfl_xor_sync(0xffffffffu, send, 4);
    }
    a[0] += __shfl_xor_sync(0xffffffffu, a[0], 2);
    a[0] += __shfl_xor_sync(0xffffffffu, a[0], 1);
}

// ---------------- precompute GEMM: g_X = x . W[:,512:768]^T ----------------
__global__ void __launch_bounds__(256) precompute_x_kernel(
    const float* __restrict__ x,
    const float* __restrict__ Wz,
    const float* __restrict__ Wr,
    const float* __restrict__ Ww)
{
    __shared__ float As[16][132];
    __shared__ float Bs[16][132];

    const int m0 = blockIdx.y * 128;
    const int n0 = blockIdx.x * 128;
    const int tid = threadIdx.x;
    const int ty = tid >> 4;
    const int tx = tid & 15;

    float acc[8][8];
#pragma unroll
    for (int i = 0; i < 8; i++)
#pragma unroll
        for (int j = 0; j < 8; j++) acc[i][j] = 0.f;

    for (int k0 = 0; k0 < 256; k0 += 16) {
#pragma unroll
        for (int q = tid; q < 512; q += 256) {
            int r  = q >> 2;
            int kq = (q & 3) << 2;
            float4 v = *(const float4*)(x + (size_t)(m0 + r) * 256 + k0 + kq);
            As[kq + 0][r] = v.x; As[kq + 1][r] = v.y;
            As[kq + 2][r] = v.z; As[kq + 3][r] = v.w;
        }
#pragma unroll
        for (int q = tid; q < 512; q += 256) {
            int r  = q >> 2;
            int kq = (q & 3) << 2;
            int n  = n0 + r;
            const float* wrow;
            if (n < 512)        wrow = Wz + (size_t)n * HX;
            else if (n < 1024)  wrow = Wr + (size_t)(n - 512) * HX;
            else                wrow = Ww + (size_t)(n - 1024) * HX;
            float4 v = *(const float4*)(wrow + 512 + k0 + kq);
            Bs[kq + 0][r] = v.x; Bs[kq + 1][r] = v.y;
            Bs[kq + 2][r] = v.z; Bs[kq + 3][r] = v.w;
        }
        __syncthreads();
#pragma unroll
        for (int kk = 0; kk < 16; kk++) {
            float a[8], b[8];
#pragma unroll
            for (int i = 0; i < 8; i++) a[i] = As[kk][ty * 8 + i];
#pragma unroll
            for (int j = 0; j < 8; j++) b[j] = Bs[kk][tx * 8 + j];
#pragma unroll
            for (int i = 0; i < 8; i++)
#pragma unroll
                for (int j = 0; j < 8; j++) acc[i][j] += a[i] * b[j];
        }
        __syncthreads();
    }

#pragma unroll
    for (int i = 0; i < 8; i++) {
        int m = m0 + ty * 8 + i;
        int t = m & 2047;
        int b = m >> 11;
        size_t base = ((size_t)t * B_ + b) * N3 + n0 + tx * 8;
        *(float4*)&g_X[base + 0] = make_float4(acc[i][0], acc[i][1], acc[i][2], acc[i][3]);
        *(float4*)&g_X[base + 4] = make_float4(acc[i][4], acc[i][5], acc[i][6], acc[i][7]);
    }
}

// ---------------- persistent recurrent kernel ----------------
__global__ void __launch_bounds__(NTHR, 1) gru_persistent_kernel(
    const float* __restrict__ h0,
    const float* __restrict__ Wz,
    const float* __restrict__ Wr,
    const float* __restrict__ Ww,
    float* __restrict__ out)
{
    extern __shared__ float sm[];
    const uint32_t sb = smem_u32(sm);
    const int tid  = threadIdx.x;
    const int wg   = tid >> 5;           // 0..15
    const int lane = tid & 31;
    const int cta  = blockIdx.x;
    const int cg   = cta & (NCG - 1);
    const int bg   = cta >> 4;
    const int b0   = bg * BPG;
    const int c0   = cg * CPG;

    // ---- cache weight h-parts: 3 x [32 rows x 512] ----
    for (int q = tid; q < 32 * 128; q += NTHR) {
        int row = q >> 7, f4 = q & 127;
        ((float4*)(sm + WR_F))[row * 128 + f4] = *(const float4*)(Wr + (size_t)(c0 + row) * HX + f4 * 4);
        ((float4*)(sm + WZ_F))[row * 128 + f4] = *(const float4*)(Wz + (size_t)(c0 + row) * HX + f4 * 4);
        ((float4*)(sm + WW_F))[row * 128 + f4] = *(const float4*)(Ww + (size_t)(c0 + row) * HX + f4 * 4);
    }
    __syncthreads();

    // flag bases (monotonic across graph replays; all group flags equal here)
    const unsigned hbase  = ld_acquire(&g_hflag[bg * 32 + cg]);
    const unsigned rhbase = ld_acquire(&g_rhflag[bg * 32 + cg]);

    // output mapping: 4-lane group owns output o = (lane>>2)&7 = c*4+b
    const int oc = (lane >> 4) & 1;       // col within warp's 2
    const int ob = (lane >> 2) & 3;       // batch within group
    const int colg = c0 + wg * 2 + oc;    // global gate column (0..511)
    const bool wr = (lane & 3) == 0;

    // prefetch x-contributions for t=0
    size_t xbase = ((size_t)0 * B_ + b0 + ob) * N3;
    float xz = __ldg(&g_X[xbase + colg]);
    float xr = __ldg(&g_X[xbase + 512 + colg]);
    float xw = __ldg(&g_X[xbase + 1024 + colg]);

    for (int t = 0; t < L_; t++) {
        const float* hsrc = (t == 0) ? h0 : (out + (size_t)(t - 1) * B_ * H_);
        float* rhbuf = g_rh[t & 1];

        // ---- wait for h(t) ----
        if (t > 0) {
            if (wg == 0) wait_flags(&g_hflag[bg * 32], hbase + (unsigned)t, lane);
            __syncthreads();
        }

        // ---- load h(t) slice directly into registers (L2, coalesced) ----
        ull hv[4][8];
#pragma unroll
        for (int b = 0; b < 4; b++)
#pragma unroll
            for (int i = 0; i < 8; i++)
                hv[b][i] = ldg64cg(hsrc + (size_t)(b0 + b) * H_ + (i * 32 + lane) * 2);
        float hval = ldg32cg(hsrc + (size_t)(b0 + ob) * H_ + colg);

        // ================= r gate =================
        {
            ull acc[2][4];
#pragma unroll
            for (int c = 0; c < 2; c++)
#pragma unroll
                for (int b = 0; b < 4; b++) acc[c][b] = 0ull;

            const uint32_t wb = sb + (WR_F + (wg * 2) * 512) * 4;
#pragma unroll
            for (int i = 0; i < 8; i++) {
                uint32_t off = (uint32_t)(i * 32 + lane) * 8u;
#pragma unroll
                for (int c = 0; c < 2; c++) {
                    ull wv = lds64(wb + c * 2048 + off);
                    fma2(acc[c][0], hv[0][i], wv);
                    fma2(acc[c][1], hv[1][i], wv);
                    fma2(acc[c][2], hv[2][i], wv);
                    fma2(acc[c][3], hv[3][i], wv);
                }
            }
            float a[8];
#pragma unroll
            for (int c = 0; c < 2; c++)
#pragma unroll
                for (int b = 0; b < 4; b++) a[c * 4 + b] = sum2(acc[c][b]);
            reduce8(a, lane);

            if (wr) {
                float r = 1.f / (1.f + __expf(-(a[0] + xr)));
                __stcg(&rhbuf[(size_t)(b0 + ob) * H_ + colg], r * hval);
            }
        }
        __syncthreads();
        if (tid == 0) st_release(&g_rhflag[bg * 32 + cg], rhbase + (unsigned)(t + 1));

        // ================= z gate (overlaps r*h exchange) =================
        float zv;
        {
            ull acc[2][4];
#pragma unroll
            for (int c = 0; c < 2; c++)
#pragma unroll
                for (int b = 0; b < 4; b++) acc[c][b] = 0ull;

            const uint32_t wb = sb + (WZ_F + (wg * 2) * 512) * 4;
#pragma unroll
            for (int i = 0; i < 8; i++) {
                uint32_t off = (uint32_t)(i * 32 + lane) * 8u;
#pragma unroll
                for (int c = 0; c < 2; c++) {
                    ull wv = lds64(wb + c * 2048 + off);
                    fma2(acc[c][0], hv[0][i], wv);
                    fma2(acc[c][1], hv[1][i], wv);
                    fma2(acc[c][2], hv[2][i], wv);
                    fma2(acc[c][3], hv[3][i], wv);
                }
            }
            float a[8];
#pragma unroll
            for (int c = 0; c < 2; c++)
#pragma unroll
                for (int b = 0; b < 4; b++) a[c * 4 + b] = sum2(acc[c][b]);
            reduce8(a, lane);
            zv = 1.f / (1.f + __expf(-(a[0] + xz)));
        }

        // ---- wait for all r*h in group, read directly into registers ----
        if (wg == 0) wait_flags(&g_rhflag[bg * 32], rhbase + (unsigned)(t + 1), lane);
        __syncthreads();
#pragma unroll
        for (int b = 0; b < 4; b++)
#pragma unroll
            for (int i = 0; i < 8; i++)
                hv[b][i] = ldg64cg(rhbuf + (size_t)(b0 + b) * H_ + (i * 32 + lane) * 2);

        // ================= w gate (candidate) + blend =================
        {
            ull acc[2][4];
#pragma unroll
            for (int c = 0; c < 2; c++)
#pragma unroll
                for (int b = 0; b < 4; b++) acc[c][b] = 0ull;

            const uint32_t wb = sb + (WW_F + (wg * 2) * 512) * 4;
#pragma unroll
            for (int i = 0; i < 8; i++) {
                uint32_t off = (uint32_t)(i * 32 + lane) * 8u;
#pragma unroll
                for (int c = 0; c < 2; c++) {
                    ull wv = lds64(wb + c * 2048 + off);
                    fma2(acc[c][0], hv[0][i], wv);
                    fma2(acc[c][1], hv[1][i], wv);
                    fma2(acc[c][2], hv[2][i], wv);
                    fma2(acc[c][3], hv[3][i], wv);
                }
            }
            float a[8];
#pragma unroll
            for (int c = 0; c < 2; c++)
#pragma unroll
                for (int b = 0; b < 4; b++) a[c * 4 + b] = sum2(acc[c][b]);
            reduce8(a, lane);

            if (wr) {
                float hh = tanhf(a[0] + xw);
                float hn = hval + zv * (hh - hval);
                __stcg(&out[((size_t)t * B_ + b0 + ob) * H_ + colg], hn);
            }
        }

        // ---- prefetch x-contributions for t+1 ----
        {
            int tn = (t + 1 < L_) ? (t + 1) : t;
            xbase = ((size_t)tn * B_ + b0 + ob) * N3;
            xz = __ldg(&g_X[xbase + colg]);
            xr = __ldg(&g_X[xbase + 512 + colg]);
            xw = __ldg(&g_X[xbase + 1024 + colg]);
        }

        __syncthreads();
        if (tid == 0) st_release(&g_hflag[bg * 32 + cg], hbase + (unsigned)(t + 1));
    }
}

// ---------------- launch ----------------
extern "C" void kernel_launch(void* const* d_in, const int* in_sizes, int n_in,
                              void* d_out, int out_size)
{
    const float* x  = (const float*)d_in[0];   // [32, 2048, 256]
    const float* h0 = (const float*)d_in[1];   // [32, 512]
    const float* Wz = (const float*)d_in[2];   // [512, 768]
    const float* Wr = (const float*)d_in[3];   // [512, 768]
    const float* Ww = (const float*)d_in[4];   // [512, 768]
    float* out = (float*)d_out;                // [2048, 32, 512]

    cudaFuncSetAttribute(gru_persistent_kernel,
                         cudaFuncAttributeMaxDynamicSharedMemorySize, SMEM_BYTES);

    dim3 pgrid(N3 / 128, (B_ * L_) / 128);     // (12, 512)
    precompute_x_kernel<<<pgrid, 256>>>(x, Wz, Wr, Ww);

    gru_persistent_kernel<<<NCG * NBG, NTHR, SMEM_BYTES>>>(h0, Wz, Wr, Ww, out);
}

// round 9
// speedup vs baseline: 1.1525x; 1.1525x over previous
#include <cuda_runtime.h>
#include <cstdint>
#include <math.h>

typedef unsigned long long ull;

// Problem constants
#define B_    32
#define L_    2048
#define I_    256
#define H_    512
#define HX    768      // H + I
#define N3    1536     // 3*H (z | r | w)
#define NCG   16       // column groups (CTAs per batch group)
#define NBG   8        // batch groups
#define BPG   4        // batches per group
#define CPG   32       // gate columns per CTA per gate
#define NTHR  256

// ---------------- device scratch ----------------
__device__ float g_X[(size_t)L_ * B_ * N3];   // precomputed x-contributions
__device__ float g_rh[2][B_ * H_];            // r*h exchange (parity buffers)
__device__ unsigned g_hflag[NBG * 32];        // h-step flags (16 per group, 1 line)
__device__ unsigned g_rhflag[NBG * 32];       // rh-step flags

// ---------------- smem layout (float offsets): weights only ----------------
#define WR_F 0                   // 32 x 512
#define WZ_F (32 * 512)
#define WW_F (64 * 512)
#define SM_FLOATS (96 * 512)
#define SMEM_BYTES (SM_FLOATS * 4)   // 196,608 B

// ---------------- asm helpers ----------------
__device__ __forceinline__ uint32_t smem_u32(const void* p) {
    uint32_t a;
    asm("{ .reg .u64 t; cvta.to.shared.u64 t, %1; cvt.u32.u64 %0, t; }" : "=r"(a) : "l"(p));
    return a;
}
__device__ __forceinline__ ull lds64(uint32_t a) {
    ull v;
    asm volatile("ld.shared.b64 %0, [%1];" : "=l"(v) : "r"(a));
    return v;
}
__device__ __forceinline__ ull ldg64cg(const void* p) {
    ull v;
    asm volatile("ld.global.cg.b64 %0, [%1];" : "=l"(v) : "l"(p));
    return v;
}
__device__ __forceinline__ float ldg32cg(const void* p) {
    float v;
    asm volatile("ld.global.cg.f32 %0, [%1];" : "=f"(v) : "l"(p));
    return v;
}
__device__ __forceinline__ void fma2(ull& acc, ull a, ull b) {
    asm volatile("fma.rn.f32x2 %0, %1, %2, %0;" : "+l"(acc) : "l"(a), "l"(b));
}
__device__ __forceinline__ float sum2(ull v) {
    float lo, hi;
    asm("mov.b64 {%0, %1}, %2;" : "=f"(lo), "=f"(hi) : "l"(v));
    return lo + hi;
}
__device__ __forceinline__ void st_release(unsigned* p, unsigned v) {
    asm volatile("st.release.gpu.u32 [%0], %1;" :: "l"(p), "r"(v) : "memory");
}
__device__ __forceinline__ unsigned ld_acquire(const unsigned* p) {
    unsigned v;
    asm volatile("ld.acquire.gpu.u32 %0, [%1];" : "=r"(v) : "l"(p) : "memory");
    return v;
}

// warp 0 polls the group's 16 flags (one 128B line); caller syncs after.
__device__ __forceinline__ void wait_flags(const unsigned* flags, unsigned target, int lane) {
    const unsigned* p = flags + (lane & 15);
    unsigned v;
    do {
        v = ld_acquire(p);
    } while (!__all_sync(0xffffffffu, (int)(v - target) >= 0));
}

// ---------------- warp reduction: 16 chains over 32 lanes ----------------
// After return: thread pair (2l, 2l+1) holds chain o = (lane>>1)&15 in a[0].
__device__ __forceinline__ void reduce16(float a[16], int lane) {
#pragma unroll
    for (int o = 0; o < 8; o++) {
        bool hi = (lane & 16);
        float send = hi ? a[o] : a[o + 8];
        float keep = hi ? a[o + 8] : a[o];
        a[o] = keep + __shfl_xor_sync(0xffffffffu, send, 16);
    }
#pragma unroll
    for (int o = 0; o < 4; o++) {
        bool hi = (lane & 8);
        float send = hi ? a[o] : a[o + 4];
        float keep = hi ? a[o + 4] : a[o];
        a[o] = keep + __shfl_xor_sync(0xffffffffu, send, 8);
    }
#pragma unroll
    for (int o = 0; o < 2; o++) {
        bool hi = (lane & 4);
        float send = hi ? a[o] : a[o + 2];
        float keep = hi ? a[o + 2] : a[o];
        a[o] = keep + __shfl_xor_sync(0xffffffffu, send, 4);
    }
    {
        bool hi = (lane & 2);
        float send = hi ? a[0] : a[1];
        float keep = hi ? a[1] : a[0];
        a[0] = keep + __shfl_xor_sync(0xffffffffu, send, 2);
    }
    a[0] += __shfl_xor_sync(0xffffffffu, a[0], 1);
}

// ---------------- precompute GEMM: g_X = x . W[:,512:768]^T ----------------
__global__ void __launch_bounds__(256) precompute_x_kernel(
    const float* __restrict__ x,
    const float* __restrict__ Wz,
    const float* __restrict__ Wr,
    const float* __restrict__ Ww)
{
    __shared__ float As[16][132];
    __shared__ float Bs[16][132];

    const int m0 = blockIdx.y * 128;
    const int n0 = blockIdx.x * 128;
    const int tid = threadIdx.x;
    const int ty = tid >> 4;
    const int tx = tid & 15;

    float acc[8][8];
#pragma unroll
    for (int i = 0; i < 8; i++)
#pragma unroll
        for (int j = 0; j < 8; j++) acc[i][j] = 0.f;

    for (int k0 = 0; k0 < 256; k0 += 16) {
#pragma unroll
        for (int q = tid; q < 512; q += 256) {
            int r  = q >> 2;
            int kq = (q & 3) << 2;
            float4 v = *(const float4*)(x + (size_t)(m0 + r) * 256 + k0 + kq);
            As[kq + 0][r] = v.x; As[kq + 1][r] = v.y;
            As[kq + 2][r] = v.z; As[kq + 3][r] = v.w;
        }
#pragma unroll
        for (int q = tid; q < 512; q += 256) {
            int r  = q >> 2;
            int kq = (q & 3) << 2;
            int n  = n0 + r;
            const float* wrow;
            if (n < 512)        wrow = Wz + (size_t)n * HX;
            else if (n < 1024)  wrow = Wr + (size_t)(n - 512) * HX;
            else                wrow = Ww + (size_t)(n - 1024) * HX;
            float4 v = *(const float4*)(wrow + 512 + k0 + kq);
            Bs[kq + 0][r] = v.x; Bs[kq + 1][r] = v.y;
            Bs[kq + 2][r] = v.z; Bs[kq + 3][r] = v.w;
        }
        __syncthreads();
#pragma unroll
        for (int kk = 0; kk < 16; kk++) {
            float a[8], b[8];
#pragma unroll
            for (int i = 0; i < 8; i++) a[i] = As[kk][ty * 8 + i];
#pragma unroll
            for (int j = 0; j < 8; j++) b[j] = Bs[kk][tx * 8 + j];
#pragma unroll
            for (int i = 0; i < 8; i++)
#pragma unroll
                for (int j = 0; j < 8; j++) acc[i][j] += a[i] * b[j];
        }
        __syncthreads();
    }

#pragma unroll
    for (int i = 0; i < 8; i++) {
        int m = m0 + ty * 8 + i;
        int t = m & 2047;
        int b = m >> 11;
        size_t base = ((size_t)t * B_ + b) * N3 + n0 + tx * 8;
        *(float4*)&g_X[base + 0] = make_float4(acc[i][0], acc[i][1], acc[i][2], acc[i][3]);
        *(float4*)&g_X[base + 4] = make_float4(acc[i][4], acc[i][5], acc[i][6], acc[i][7]);
    }
}

// ---------------- persistent recurrent kernel ----------------
__global__ void __launch_bounds__(NTHR, 1) gru_persistent_kernel(
    const float* __restrict__ h0,
    const float* __restrict__ Wz,
    const float* __restrict__ Wr,
    const float* __restrict__ Ww,
    float* __restrict__ out)
{
    extern __shared__ float sm[];
    const uint32_t sb = smem_u32(sm);
    const int tid  = threadIdx.x;
    const int wg   = tid >> 5;
    const int lane = tid & 31;
    const int cta  = blockIdx.x;
    const int cg   = cta & (NCG - 1);
    const int bg   = cta >> 4;
    const int b0   = bg * BPG;
    const int c0   = cg * CPG;

    // ---- cache weight h-parts: 3 x [32 rows x 512] ----
    for (int q = tid; q < 32 * 128; q += NTHR) {
        int row = q >> 7, f4 = q & 127;
        ((float4*)(sm + WR_F))[row * 128 + f4] = *(const float4*)(Wr + (size_t)(c0 + row) * HX + f4 * 4);
        ((float4*)(sm + WZ_F))[row * 128 + f4] = *(const float4*)(Wz + (size_t)(c0 + row) * HX + f4 * 4);
        ((float4*)(sm + WW_F))[row * 128 + f4] = *(const float4*)(Ww + (size_t)(c0 + row) * HX + f4 * 4);
    }
    __syncthreads();

    // flag bases (monotonic across graph replays)
    const unsigned hbase  = ld_acquire(&g_hflag[bg * 32 + cg]);
    const unsigned rhbase = ld_acquire(&g_rhflag[bg * 32 + cg]);

    // output mapping: even lanes own output o = (lane>>1)&15 = c*4+b
    const int o   = (lane >> 1) & 15;
    const int oc  = o >> 2;              // col within warp's 4
    const int ob  = o & 3;               // batch within group
    const int colg = c0 + wg * 4 + oc;   // global gate column (0..511)
    const bool wr = !(lane & 1);

    // prefetch x-contributions for t=0
    size_t xbase = ((size_t)0 * B_ + b0 + ob) * N3;
    float xz = __ldg(&g_X[xbase + colg]);
    float xr = __ldg(&g_X[xbase + 512 + colg]);
    float xw = __ldg(&g_X[xbase + 1024 + colg]);

    // own h element (register-carried across steps)
    float hval = ldg32cg(h0 + (size_t)(b0 + ob) * H_ + colg);

    for (int t = 0; t < L_; t++) {
        const float* hsrc = (t == 0) ? h0 : (out + (size_t)(t - 1) * B_ * H_);
        float* rhbuf = g_rh[t & 1];

        // ---- wait for h(t) from all peers ----
        if (t > 0) {
            if (wg == 0) wait_flags(&g_hflag[bg * 32], hbase + (unsigned)t, lane);
            __syncthreads();
        }

        // ---- load h(t) slice directly into registers (L2, coalesced) ----
        ull hv[4][8];
#pragma unroll
        for (int b = 0; b < 4; b++)
#pragma unroll
            for (int i = 0; i < 8; i++)
                hv[b][i] = ldg64cg(hsrc + (size_t)(b0 + b) * H_ + (i * 32 + lane) * 2);

        // ================= r gate =================
        {
            ull acc[4][4];
#pragma unroll
            for (int c = 0; c < 4; c++)
#pragma unroll
                for (int b = 0; b < 4; b++) acc[c][b] = 0ull;

            const uint32_t wb = sb + (WR_F + (wg * 4) * 512) * 4;
#pragma unroll
            for (int i = 0; i < 8; i++) {
                uint32_t off = (uint32_t)(i * 32 + lane) * 8u;
#pragma unroll
                for (int c = 0; c < 4; c++) {
                    ull wv = lds64(wb + c * 2048 + off);
                    fma2(acc[c][0], hv[0][i], wv);
                    fma2(acc[c][1], hv[1][i], wv);
                    fma2(acc[c][2], hv[2][i], wv);
                    fma2(acc[c][3], hv[3][i], wv);
                }
            }
            float a[16];
#pragma unroll
            for (int c = 0; c < 4; c++)
#pragma unroll
                for (int b = 0; b < 4; b++) a[c * 4 + b] = sum2(acc[c][b]);
            reduce16(a, lane);

            if (wr) {
                float r = 1.f / (1.f + __expf(-(a[0] + xr)));
                __stcg(&rhbuf[(size_t)(b0 + ob) * H_ + colg], r * hval);
            }
        }
        __syncthreads();
        if (tid == 0) st_release(&g_rhflag[bg * 32 + cg], rhbase + (unsigned)(t + 1));

        // ================= z gate (overlaps r*h exchange) =================
        float zv;
        {
            ull acc[4][4];
#pragma unroll
            for (int c = 0; c < 4; c++)
#pragma unroll
                for (int b = 0; b < 4; b++) acc[c][b] = 0ull;

            const uint32_t wb = sb + (WZ_F + (wg * 4) * 512) * 4;
#pragma unroll
            for (int i = 0; i < 8; i++) {
                uint32_t off = (uint32_t)(i * 32 + lane) * 8u;
#pragma unroll
                for (int c = 0; c < 4; c++) {
                    ull wv = lds64(wb + c * 2048 + off);
                    fma2(acc[c][0], hv[0][i], wv);
                    fma2(acc[c][1], hv[1][i], wv);
                    fma2(acc[c][2], hv[2][i], wv);
                    fma2(acc[c][3], hv[3][i], wv);
                }
            }
            float a[16];
#pragma unroll
            for (int c = 0; c < 4; c++)
#pragma unroll
                for (int b = 0; b < 4; b++) a[c * 4 + b] = sum2(acc[c][b]);
            reduce16(a, lane);
            zv = 1.f / (1.f + __expf(-(a[0] + xz)));
        }

        // ---- wait for all r*h in group, read directly into registers ----
        if (wg == 0) wait_flags(&g_rhflag[bg * 32], rhbase + (unsigned)(t + 1), lane);
        __syncthreads();
        ull rb[4][8];
#pragma unroll
        for (int b = 0; b < 4; b++)
#pragma unroll
            for (int i = 0; i < 8; i++)
                rb[b][i] = ldg64cg(rhbuf + (size_t)(b0 + b) * H_ + (i * 32 + lane) * 2);

        // ================= w gate (candidate) + blend =================
        float hn = 0.f;
        {
            ull acc[4][4];
#pragma unroll
            for (int c = 0; c < 4; c++)
#pragma unroll
                for (int b = 0; b < 4; b++) acc[c][b] = 0ull;

            const uint32_t wb = sb + (WW_F + (wg * 4) * 512) * 4;
#pragma unroll
            for (int i = 0; i < 8; i++) {
                uint32_t off = (uint32_t)(i * 32 + lane) * 8u;
#pragma unroll
                for (int c = 0; c < 4; c++) {
                    ull wv = lds64(wb + c * 2048 + off);
                    fma2(acc[c][0], rb[0][i], wv);
                    fma2(acc[c][1], rb[1][i], wv);
                    fma2(acc[c][2], rb[2][i], wv);
                    fma2(acc[c][3], rb[3][i], wv);
                }
            }
            float a[16];
#pragma unroll
            for (int c = 0; c < 4; c++)
#pragma unroll
                for (int b = 0; b < 4; b++) a[c * 4 + b] = sum2(acc[c][b]);
            reduce16(a, lane);

            if (wr) {
                float hh = tanhf(a[0] + xw);
                hn = hval + zv * (hh - hval);
                __stcg(&out[((size_t)t * B_ + b0 + ob) * H_ + colg], hn);
            }
        }
        // carry own h element to next step (broadcast from even lane of the pair)
        hval = __shfl_sync(0xffffffffu, hn, lane & 30);

        // ---- prefetch x-contributions for t+1 ----
        {
            int tn = (t + 1 < L_) ? (t + 1) : t;
            xbase = ((size_t)tn * B_ + b0 + ob) * N3;
            xz = __ldg(&g_X[xbase + colg]);
            xr = __ldg(&g_X[xbase + 512 + colg]);
            xw = __ldg(&g_X[xbase + 1024 + colg]);
        }

        __syncthreads();
        if (tid == 0) st_release(&g_hflag[bg * 32 + cg], hbase + (unsigned)(t + 1));
    }
}

// ---------------- launch ----------------
extern "C" void kernel_launch(void* const* d_in, const int* in_sizes, int n_in,
                              void* d_out, int out_size)
{
    const float* x  = (const float*)d_in[0];   // [32, 2048, 256]
    const float* h0 = (const float*)d_in[1];   // [32, 512]
    const float* Wz = (const float*)d_in[2];   // [512, 768]
    const float* Wr = (const float*)d_in[3];   // [512, 768]
    const float* Ww = (const float*)d_in[4];   // [512, 768]
    float* out = (float*)d_out;                // [2048, 32, 512]

    cudaFuncSetAttribute(gru_persistent_kernel,
                         cudaFuncAttributeMaxDynamicSharedMemorySize, SMEM_BYTES);

    dim3 pgrid(N3 / 128, (B_ * L_) / 128);     // (12, 512)
    precompute_x_kernel<<<pgrid, 256>>>(x, Wz, Wr, Ww);

    gru_persistent_kernel<<<NCG * NBG, NTHR, SMEM_BYTES>>>(h0, Wz, Wr, Ww, out);
}

// round 10
// speedup vs baseline: 1.2359x; 1.0723x over previous
#include <cuda_runtime.h>
#include <cstdint>
#include <math.h>

typedef unsigned long long ull;

// Problem constants
#define B_    32
#define L_    2048
#define I_    256
#define H_    512
#define HX    768      // H + I
#define N3    1536     // 3*H (z | r | w)
#define NCG   16       // column groups (CTAs per batch group)
#define NBG2  16       // batch groups (2 batches each)
#define BPG   2        // batches per group
#define CPG   32       // gate columns per CTA per gate
#define NTHR  512      // two 256-thread halves, one per batch group

// ---------------- device scratch ----------------
__device__ float g_X[(size_t)L_ * B_ * N3];   // precomputed x-contributions
__device__ float g_rh[2][B_ * H_];            // r*h exchange (parity buffers)
__device__ unsigned g_hflag[NBG2 * 32];       // h-step flags (16 per group, 1 line)
__device__ unsigned g_rhflag[NBG2 * 32];      // rh-step flags

// ---------------- smem layout (float offsets): weights only (shared by halves) ----
#define WR_F 0                   // 32 x 512
#define WZ_F (32 * 512)
#define WW_F (64 * 512)
#define SM_FLOATS (96 * 512)
#define SMEM_BYTES (SM_FLOATS * 4)   // 196,608 B

// ---------------- asm helpers ----------------
__device__ __forceinline__ uint32_t smem_u32(const void* p) {
    uint32_t a;
    asm("{ .reg .u64 t; cvta.to.shared.u64 t, %1; cvt.u32.u64 %0, t; }" : "=r"(a) : "l"(p));
    return a;
}
__device__ __forceinline__ ull lds64(uint32_t a) {
    ull v;
    asm volatile("ld.shared.b64 %0, [%1];" : "=l"(v) : "r"(a));
    return v;
}
__device__ __forceinline__ ull ldg64cg(const void* p) {
    ull v;
    asm volatile("ld.global.cg.b64 %0, [%1];" : "=l"(v) : "l"(p));
    return v;
}
__device__ __forceinline__ float ldg32cg(const void* p) {
    float v;
    asm volatile("ld.global.cg.f32 %0, [%1];" : "=f"(v) : "l"(p));
    return v;
}
__device__ __forceinline__ void fma2(ull& acc, ull a, ull b) {
    asm volatile("fma.rn.f32x2 %0, %1, %2, %0;" : "+l"(acc) : "l"(a), "l"(b));
}
__device__ __forceinline__ float sum2(ull v) {
    float lo, hi;
    asm("mov.b64 {%0, %1}, %2;" : "=f"(lo), "=f"(hi) : "l"(v));
    return lo + hi;
}
__device__ __forceinline__ void st_release(unsigned* p, unsigned v) {
    asm volatile("st.release.gpu.u32 [%0], %1;" :: "l"(p), "r"(v) : "memory");
}
__device__ __forceinline__ unsigned ld_acquire(const unsigned* p) {
    unsigned v;
    asm volatile("ld.acquire.gpu.u32 %0, [%1];" : "=r"(v) : "l"(p) : "memory");
    return v;
}
// half-CTA named barrier (256 threads)
__device__ __forceinline__ void barx(int id) {
    asm volatile("bar.sync %0, 256;" :: "r"(id) : "memory");
}
// poll warp: lanes poll the group's 16 flags (one 128B line)
__device__ __forceinline__ void wait_flags(const unsigned* flags, unsigned target, int lane) {
    const unsigned* p = flags + (lane & 15);
    unsigned v;
    do {
        v = ld_acquire(p);
    } while (!__all_sync(0xffffffffu, (int)(v - target) >= 0));
}

// ---------------- warp reduction: 8 chains over 32 lanes ----------------
// After return: 4-lane group holds chain o = (lane>>2)&7 in a[0].
__device__ __forceinline__ void reduce8(float a[8], int lane) {
#pragma unroll
    for (int o = 0; o < 4; o++) {
        bool hi = (lane & 16);
        float send = hi ? a[o] : a[o + 4];
        float keep = hi ? a[o + 4] : a[o];
        a[o] = keep + __shfl_xor_sync(0xffffffffu, send, 16);
    }
#pragma unroll
    for (int o = 0; o < 2; o++) {
        bool hi = (lane & 8);
        float send = hi ? a[o] : a[o + 2];
        float keep = hi ? a[o + 2] : a[o];
        a[o] = keep + __shfl_xor_sync(0xffffffffu, send, 8);
    }
    {
        bool hi = (lane & 4);
        float send = hi ? a[0] : a[1];
        float keep = hi ? a[1] : a[0];
        a[0] = keep + __shfl_xor_sync(0xffffffffu, send, 4);
    }
    a[0] += __shfl_xor_sync(0xffffffffu, a[0], 2);
    a[0] += __shfl_xor_sync(0xffffffffu, a[0], 1);
}

// ---------------- precompute GEMM: g_X = x . W[:,512:768]^T ----------------
__global__ void __launch_bounds__(256) precompute_x_kernel(
    const float* __restrict__ x,
    const float* __restrict__ Wz,
    const float* __restrict__ Wr,
    const float* __restrict__ Ww)
{
    __shared__ float As[16][132];
    __shared__ float Bs[16][132];

    const int m0 = blockIdx.y * 128;
    const int n0 = blockIdx.x * 128;
    const int tid = threadIdx.x;
    const int ty = tid >> 4;
    const int tx = tid & 15;

    float acc[8][8];
#pragma unroll
    for (int i = 0; i < 8; i++)
#pragma unroll
        for (int j = 0; j < 8; j++) acc[i][j] = 0.f;

    for (int k0 = 0; k0 < 256; k0 += 16) {
#pragma unroll
        for (int q = tid; q < 512; q += 256) {
            int r  = q >> 2;
            int kq = (q & 3) << 2;
            float4 v = *(const float4*)(x + (size_t)(m0 + r) * 256 + k0 + kq);
            As[kq + 0][r] = v.x; As[kq + 1][r] = v.y;
            As[kq + 2][r] = v.z; As[kq + 3][r] = v.w;
        }
#pragma unroll
        for (int q = tid; q < 512; q += 256) {
            int r  = q >> 2;
            int kq = (q & 3) << 2;
            int n  = n0 + r;
            const float* wrow;
            if (n < 512)        wrow = Wz + (size_t)n * HX;
            else if (n < 1024)  wrow = Wr + (size_t)(n - 512) * HX;
            else                wrow = Ww + (size_t)(n - 1024) * HX;
            float4 v = *(const float4*)(wrow + 512 + k0 + kq);
            Bs[kq + 0][r] = v.x; Bs[kq + 1][r] = v.y;
            Bs[kq + 2][r] = v.z; Bs[kq + 3][r] = v.w;
        }
        __syncthreads();
#pragma unroll
        for (int kk = 0; kk < 16; kk++) {
            float a[8], b[8];
#pragma unroll
            for (int i = 0; i < 8; i++) a[i] = As[kk][ty * 8 + i];
#pragma unroll
            for (int j = 0; j < 8; j++) b[j] = Bs[kk][tx * 8 + j];
#pragma unroll
            for (int i = 0; i < 8; i++)
#pragma unroll
                for (int j = 0; j < 8; j++) acc[i][j] += a[i] * b[j];
        }
        __syncthreads();
    }

#pragma unroll
    for (int i = 0; i < 8; i++) {
        int m = m0 + ty * 8 + i;
        int t = m & 2047;
        int b = m >> 11;
        size_t base = ((size_t)t * B_ + b) * N3 + n0 + tx * 8;
        *(float4*)&g_X[base + 0] = make_float4(acc[i][0], acc[i][1], acc[i][2], acc[i][3]);
        *(float4*)&g_X[base + 4] = make_float4(acc[i][4], acc[i][5], acc[i][6], acc[i][7]);
    }
}

// ---------------- persistent recurrent kernel: 128 CTAs x 512 thr ----------------
__global__ void __launch_bounds__(NTHR, 1) gru_persistent_kernel(
    const float* __restrict__ h0,
    const float* __restrict__ Wz,
    const float* __restrict__ Wr,
    const float* __restrict__ Ww,
    float* __restrict__ out)
{
    extern __shared__ float sm[];
    const uint32_t sb = smem_u32(sm);
    const int tid  = threadIdx.x;
    const int wg   = tid >> 5;           // 0..15
    const int lane = tid & 31;
    const int cta  = blockIdx.x;
    const int cg   = cta & (NCG - 1);    // column group 0..15
    const int pair = cta >> 4;           // 0..7
    const int hf   = wg >> 3;            // half 0/1
    const int lwg  = wg & 7;             // local warp 0..7
    const int g    = pair * 2 + hf;      // batch group 0..15
    const int b0   = g * BPG;            // first global batch
    const int c0   = cg * CPG;
    const int barid = 1 + hf;            // named barrier per half

    // ---- cache weight h-parts: 3 x [32 rows x 512] (shared by both halves) ----
    for (int q = tid; q < 32 * 128; q += NTHR) {
        int row = q >> 7, f4 = q & 127;
        ((float4*)(sm + WR_F))[row * 128 + f4] = *(const float4*)(Wr + (size_t)(c0 + row) * HX + f4 * 4);
        ((float4*)(sm + WZ_F))[row * 128 + f4] = *(const float4*)(Wz + (size_t)(c0 + row) * HX + f4 * 4);
        ((float4*)(sm + WW_F))[row * 128 + f4] = *(const float4*)(Ww + (size_t)(c0 + row) * HX + f4 * 4);
    }
    __syncthreads();

    // flag bases (monotonic across graph replays)
    const unsigned hbase  = ld_acquire(&g_hflag[g * 32 + cg]);
    const unsigned rhbase = ld_acquire(&g_rhflag[g * 32 + cg]);

    // output mapping: 4-lane group owns chain o = (lane>>2)&7 = oc*2+ob
    const int o   = (lane >> 2) & 7;
    const int oc  = o >> 1;              // col within warp's 4
    const int ob  = o & 1;               // batch within group
    const int colg = c0 + lwg * 4 + oc;  // global gate column (0..511)
    const bool wr = (lane & 3) == 0;

    // prefetch x-contributions for t=0
    size_t xbase = ((size_t)0 * B_ + b0 + ob) * N3;
    float xz = __ldg(&g_X[xbase + colg]);
    float xr = __ldg(&g_X[xbase + 512 + colg]);
    float xw = __ldg(&g_X[xbase + 1024 + colg]);

    // own h element (register-carried across steps)
    float hval = ldg32cg(h0 + (size_t)(b0 + ob) * H_ + colg);

    for (int t = 0; t < L_; t++) {
        const float* hsrc = (t == 0) ? h0 : (out + (size_t)(t - 1) * B_ * H_);
        float* rhbuf = g_rh[t & 1];

        // ---- wait for h(t) from all peers of this group ----
        if (t > 0) {
            if (lwg == 0) wait_flags(&g_hflag[g * 32], hbase + (unsigned)t, lane);
            barx(barid);
        }

        // ---- load h(t) slice directly into registers (L2, coalesced) ----
        ull hv[2][8];
#pragma unroll
        for (int b = 0; b < 2; b++)
#pragma unroll
            for (int i = 0; i < 8; i++)
                hv[b][i] = ldg64cg(hsrc + (size_t)(b0 + b) * H_ + (i * 32 + lane) * 2);

        // ================= r gate =================
        {
            ull acc[4][2];
#pragma unroll
            for (int c = 0; c < 4; c++)
#pragma unroll
                for (int b = 0; b < 2; b++) acc[c][b] = 0ull;

            const uint32_t wb = sb + (WR_F + (lwg * 4) * 512) * 4;
#pragma unroll
            for (int i = 0; i < 8; i++) {
                uint32_t off = (uint32_t)(i * 32 + lane) * 8u;
#pragma unroll
                for (int c = 0; c < 4; c++) {
                    ull wv = lds64(wb + c * 2048 + off);
                    fma2(acc[c][0], hv[0][i], wv);
                    fma2(acc[c][1], hv[1][i], wv);
                }
            }
            float a[8];
#pragma unroll
            for (int c = 0; c < 4; c++)
#pragma unroll
                for (int b = 0; b < 2; b++) a[c * 2 + b] = sum2(acc[c][b]);
            reduce8(a, lane);

            if (wr) {
                float r = 1.f / (1.f + __expf(-(a[0] + xr)));
                __stcg(&rhbuf[(size_t)(b0 + ob) * H_ + colg], r * hval);
            }
        }
        barx(barid);
        if ((tid & 255) == 0) st_release(&g_rhflag[g * 32 + cg], rhbase + (unsigned)(t + 1));

        // ================= z gate (overlaps r*h exchange) =================
        float zv;
        {
            ull acc[4][2];
#pragma unroll
            for (int c = 0; c < 4; c++)
#pragma unroll
                for (int b = 0; b < 2; b++) acc[c][b] = 0ull;

            const uint32_t wb = sb + (WZ_F + (lwg * 4) * 512) * 4;
#pragma unroll
            for (int i = 0; i < 8; i++) {
                uint32_t off = (uint32_t)(i * 32 + lane) * 8u;
#pragma unroll
                for (int c = 0; c < 4; c++) {
                    ull wv = lds64(wb + c * 2048 + off);
                    fma2(acc[c][0], hv[0][i], wv);
                    fma2(acc[c][1], hv[1][i], wv);
                }
            }
            float a[8];
#pragma unroll
            for (int c = 0; c < 4; c++)
#pragma unroll
                for (int b = 0; b < 2; b++) a[c * 2 + b] = sum2(acc[c][b]);
            reduce8(a, lane);
            zv = 1.f / (1.f + __expf(-(a[0] + xz)));
        }

        // ---- wait for this group's r*h, read directly into registers ----
        if (lwg == 0) wait_flags(&g_rhflag[g * 32], rhbase + (unsigned)(t + 1), lane);
        barx(barid);
        ull rb[2][8];
#pragma unroll
        for (int b = 0; b < 2; b++)
#pragma unroll
            for (int i = 0; i < 8; i++)
                rb[b][i] = ldg64cg(rhbuf + (size_t)(b0 + b) * H_ + (i * 32 + lane) * 2);

        // ================= w gate (candidate) + blend =================
        float hn = 0.f;
        {
            ull acc[4][2];
#pragma unroll
            for (int c = 0; c < 4; c++)
#pragma unroll
                for (int b = 0; b < 2; b++) acc[c][b] = 0ull;

            const uint32_t wb = sb + (WW_F + (lwg * 4) * 512) * 4;
#pragma unroll
            for (int i = 0; i < 8; i++) {
                uint32_t off = (uint32_t)(i * 32 + lane) * 8u;
#pragma unroll
                for (int c = 0; c < 4; c++) {
                    ull wv = lds64(wb + c * 2048 + off);
                    fma2(acc[c][0], rb[0][i], wv);
                    fma2(acc[c][1], rb[1][i], wv);
                }
            }
            float a[8];
#pragma unroll
            for (int c = 0; c < 4; c++)
#pragma unroll
                for (int b = 0; b < 2; b++) a[c * 2 + b] = sum2(acc[c][b]);
            reduce8(a, lane);

            if (wr) {
                float hh = tanhf(a[0] + xw);
                hn = hval + zv * (hh - hval);
                __stcg(&out[((size_t)t * B_ + b0 + ob) * H_ + colg], hn);
            }
        }
        // carry own h element (broadcast within 4-lane group from lane&3==0)
        hval = __shfl_sync(0xffffffffu, hn, lane & 28);

        // ---- prefetch x-contributions for t+1 ----
        {
            int tn = (t + 1 < L_) ? (t + 1) : t;
            xbase = ((size_t)tn * B_ + b0 + ob) * N3;
            xz = __ldg(&g_X[xbase + colg]);
            xr = __ldg(&g_X[xbase + 512 + colg]);
            xw = __ldg(&g_X[xbase + 1024 + colg]);
        }

        barx(barid);
        if ((tid & 255) == 0) st_release(&g_hflag[g * 32 + cg], hbase + (unsigned)(t + 1));
    }
}

// ---------------- launch ----------------
extern "C" void kernel_launch(void* const* d_in, const int* in_sizes, int n_in,
                              void* d_out, int out_size)
{
    const float* x  = (const float*)d_in[0];   // [32, 2048, 256]
    const float* h0 = (const float*)d_in[1];   // [32, 512]
    const float* Wz = (const float*)d_in[2];   // [512, 768]
    const float* Wr = (const float*)d_in[3];   // [512, 768]
    const float* Ww = (const float*)d_in[4];   // [512, 768]
    float* out = (float*)d_out;                // [2048, 32, 512]

    cudaFuncSetAttribute(gru_persistent_kernel,
                         cudaFuncAttributeMaxDynamicSharedMemorySize, SMEM_BYTES);

    dim3 pgrid(N3 / 128, (B_ * L_) / 128);     // (12, 512)
    precompute_x_kernel<<<pgrid, 256>>>(x, Wz, Wr, Ww);

    gru_persistent_kernel<<<NCG * 8, NTHR, SMEM_BYTES>>>(h0, Wz, Wr, Ww, out);
}